// round 15
// baseline (speedup 1.0000x reference)
#include <cuda_runtime.h>
#include <cuda_fp16.h>
#include <cstdint>

#define E_MAX 20000
#define FD 128
#define H1D 64
#define H2D 32
#define DD 16
#define LN_EPS 1e-5f
#define ROWP 72   // halves per h1 row (144 B): ldmatrix rows shift 4 banks/row

// Scratch: precomputed A = ef@W1[:128] + b1, B = ef@W1[128:]
__device__ float g_A[E_MAX * H1D];
__device__ float g_B[E_MAX * H1D];

// ---------------------------------------------------------------------------
// Helpers
// ---------------------------------------------------------------------------
__device__ __forceinline__ uint32_t smem_u32(const void* p) {
    return (uint32_t)__cvta_generic_to_shared(p);
}
__device__ __forceinline__ void ldmatrix_x4(uint32_t& a0, uint32_t& a1,
                                            uint32_t& a2, uint32_t& a3,
                                            uint32_t addr) {
    asm volatile("ldmatrix.sync.aligned.m8n8.x4.shared.b16 {%0,%1,%2,%3}, [%4];"
                 : "=r"(a0), "=r"(a1), "=r"(a2), "=r"(a3) : "r"(addr));
}
__device__ __forceinline__ void mma16816(float* c,
                                         uint32_t a0, uint32_t a1, uint32_t a2, uint32_t a3,
                                         uint32_t b0, uint32_t b1) {
    asm volatile("mma.sync.aligned.m16n8k16.row.col.f32.f16.f16.f32 "
                 "{%0,%1,%2,%3}, {%4,%5,%6,%7}, {%8,%9}, {%0,%1,%2,%3};"
                 : "+f"(c[0]), "+f"(c[1]), "+f"(c[2]), "+f"(c[3])
                 : "r"(a0), "r"(a1), "r"(a2), "r"(a3), "r"(b0), "r"(b1));
}
__device__ __forceinline__ uint32_t packh2(float lo, float hi) {
    __half2 h = __floats2half2_rn(lo, hi);
    return *reinterpret_cast<uint32_t*>(&h);
}

// ---------------------------------------------------------------------------
// Precompute via HMMA with ef hi/lo fp16 split (exact ef, W1 fp16).
// R13's direct-LDG fragment build (proven fastest), amortized over FOUR
// 32-edge tiles per block (128 edges/block, 157 blocks): total fragment
// LDG traffic cut 4x vs R13.
// Warp w owns n'-tiles 4w..4w+3 of W' = [128k x 128n']
// (n'<64 -> W1[k][n'] -> g_A; n'>=64 -> W1[128+k][n'-64] -> g_B).
// ---------------------------------------------------------------------------
__global__ void __launch_bounds__(128)
precompute_kernel(const float* __restrict__ ef,
                  const float* __restrict__ W1,
                  const float* __restrict__ b1,
                  int E) {
    __shared__ __half efhi[32 * FD];   // 8 KB, XOR-swizzled 16B chunks
    __shared__ __half eflo[32 * FD];   // 8 KB

    const int tid  = threadIdx.x;
    const int warp = tid >> 5;
    const int lane = tid & 31;
    const int qr   = lane & 3;
    const int qc   = lane >> 2;

    // W' B-fragments in registers: wf[s][t] for kstep s, local ntile t.
    uint2 wf[8][4];
    float2 bias[4];
#pragma unroll
    for (int s = 0; s < 8; ++s)
#pragma unroll
        for (int t = 0; t < 4; ++t) {
            const int np = 8 * (4 * warp + t) + qc;
            const int k0 = 16 * s + 2 * qr;
            const int base = (np < H1D) ? 0 : FD;
            const int col  = (np < H1D) ? np : np - H1D;
            wf[s][t] = make_uint2(
                packh2(W1[(base + k0 + 0) * H1D + col], W1[(base + k0 + 1) * H1D + col]),
                packh2(W1[(base + k0 + 8) * H1D + col], W1[(base + k0 + 9) * H1D + col]));
        }
#pragma unroll
    for (int t = 0; t < 4; ++t) {
        if (warp < 2) {
            const int n0 = 8 * (4 * warp + t) + 2 * qr;
            bias[t] = make_float2(b1[n0], b1[n0 + 1]);
        } else {
            bias[t] = make_float2(0.f, 0.f);
        }
    }

    const int lrow = (lane & 7) | (((lane >> 3) & 1) << 3);
    const int cb   = (lane >> 4) & 1;
    const uint32_t hibase = smem_u32(efhi);
    const uint32_t lobase = smem_u32(eflo);

#pragma unroll 1
    for (int tile = 0; tile < 4; ++tile) {
        const int e0 = blockIdx.x * 128 + tile * 32;

        // Stage ef tile: 4 threads/edge row, hi/lo fp16 split, XOR swizzle.
        {
            const int r  = tid >> 2;
            const int kq = tid & 3;
            const int eg = e0 + r;
            const float4* src = reinterpret_cast<const float4*>(ef + (size_t)eg * FD);
#pragma unroll
            for (int q = 0; q < 4; ++q) {
                const int c = kq * 4 + q;
                float4 x0 = make_float4(0.f, 0.f, 0.f, 0.f), x1 = x0;
                if (eg < E) { x0 = src[c * 2]; x1 = src[c * 2 + 1]; }
                const float f[8] = {x0.x, x0.y, x0.z, x0.w, x1.x, x1.y, x1.z, x1.w};
                __half hh[8], hl[8];
#pragma unroll
                for (int i = 0; i < 8; ++i) {
                    hh[i] = __float2half_rn(f[i]);
                    hl[i] = __float2half_rn(f[i] - __half2float(hh[i]));
                }
                const int sc = c ^ (r & 7);
                *reinterpret_cast<uint4*>(&efhi[r * FD + sc * 8]) =
                    *reinterpret_cast<const uint4*>(hh);
                *reinterpret_cast<uint4*>(&eflo[r * FD + sc * 8]) =
                    *reinterpret_cast<const uint4*>(hl);
            }
        }
        __syncthreads();

#pragma unroll
        for (int mt = 0; mt < 2; ++mt) {
            const int r2 = 16 * mt + lrow;
            const int rx = r2 & 7;
            float acc[4][4];
#pragma unroll
            for (int t = 0; t < 4; ++t)
#pragma unroll
                for (int e = 0; e < 4; ++e) acc[t][e] = 0.f;

#pragma unroll
            for (int s = 0; s < 8; ++s) {
                const uint32_t off =
                    (uint32_t)(r2 * FD + ((2 * s + cb) ^ rx) * 8) * 2u;
                uint32_t h0, h1, h2, h3, l0, l1, l2, l3;
                ldmatrix_x4(h0, h1, h2, h3, hibase + off);
                ldmatrix_x4(l0, l1, l2, l3, lobase + off);
#pragma unroll
                for (int t = 0; t < 4; ++t) {
                    mma16816(acc[t], h0, h1, h2, h3, wf[s][t].x, wf[s][t].y);
                    mma16816(acc[t], l0, l1, l2, l3, wf[s][t].x, wf[s][t].y);
                }
            }

            const int rg0 = e0 + 16 * mt + qc;
            const int rg1 = rg0 + 8;
            float* const dst = (warp < 2) ? g_A : g_B;
#pragma unroll
            for (int t = 0; t < 4; ++t) {
                const int np  = 8 * (4 * warp + t) + 2 * qr;
                const int col = (warp < 2) ? np : np - H1D;
                if (rg0 < E) {
                    *reinterpret_cast<float2*>(&dst[(size_t)rg0 * H1D + col]) =
                        make_float2(acc[t][0] + bias[t].x, acc[t][1] + bias[t].y);
                }
                if (rg1 < E) {
                    *reinterpret_cast<float2*>(&dst[(size_t)rg1 * H1D + col]) =
                        make_float2(acc[t][2] + bias[t].x, acc[t][3] + bias[t].y);
                }
            }
        }
        __syncthreads();   // all mma reads done before next tile restage
    }
}

// ---------------------------------------------------------------------------
// Main kernel: R14 verbatim (store fast path; regs 60; 8 CTAs/SM).
// ---------------------------------------------------------------------------
__global__ void __launch_bounds__(128, 8)
pairs_kernel(const int* __restrict__ pi, const int* __restrict__ pj,
             const float* __restrict__ g1, const float* __restrict__ be1,
             const float* __restrict__ W2, const float* __restrict__ b2,
             const float* __restrict__ g2, const float* __restrict__ be2,
             const float* __restrict__ W3, const float* __restrict__ b3,
             float* __restrict__ out, int P) {
    __shared__ __half h1[4][32 * ROWP];     // 18432 B (aliased diag after use)
    __shared__ uint2 W2fr[4 * 4 * 32];      // 4096 B: [s][t][lane]
    __shared__ uint2 W3fr[2 * 2 * 32];      // 1024 B: [s][u][lane]
    __shared__ float g1s[H1D], be1s[H1D], b2s[H2D], g2s[H2D], be2s[H2D], b3s[DD];
    __shared__ int sidxi[128], sidxj[128];

    const int tid  = threadIdx.x;
    const int warp = tid >> 5;
    const int lane = tid & 31;
    const int qr   = lane & 3;
    const int qc   = lane >> 2;

    for (int idx = tid; idx < 4 * 4 * 32; idx += 128) {
        const int ln = idx & 31, t = (idx >> 5) & 3, s = idx >> 7;
        const int k0 = 16 * s + 2 * (ln & 3);
        const int n  = 8 * t + (ln >> 2);
        W2fr[idx] = make_uint2(
            packh2(W2[(k0 + 0) * H2D + n], W2[(k0 + 1) * H2D + n]),
            packh2(W2[(k0 + 8) * H2D + n], W2[(k0 + 9) * H2D + n]));
    }
    if (tid < 2 * 2 * 32) {
        const int idx = tid;
        const int ln = idx & 31, u = (idx >> 5) & 1, s = idx >> 6;
        const int k0 = 16 * s + 2 * (ln & 3);
        const int n  = 8 * u + (ln >> 2);
        W3fr[idx] = make_uint2(
            packh2(W3[(k0 + 0) * DD + n], W3[(k0 + 1) * DD + n]),
            packh2(W3[(k0 + 8) * DD + n], W3[(k0 + 9) * DD + n]));
    }
    if (tid < H1D) { g1s[tid] = g1[tid]; be1s[tid] = be1[tid]; }
    if (tid < H2D) { b2s[tid] = b2[tid]; g2s[tid] = g2[tid]; be2s[tid] = be2[tid]; }
    if (tid < DD)  { b3s[tid] = b3[tid]; }
    {
        const int gp = blockIdx.x * 128 + tid;
        const int safe = (gp < P) ? gp : 0;
        sidxi[tid] = pi[safe];
        sidxj[tid] = pj[safe];
    }
    __syncthreads();

    // Gather + fused LN1: 4 pairs/iter; 8 lanes per pair cover 8 channels.
    const int lc8 = lane & 7;
    const int sub = lane >> 3;
    __half* h1w = h1[warp];
    const int* myidxi = sidxi + warp * 32;
    const int* myidxj = sidxj + warp * 32;

#pragma unroll
    for (int p = 0; p < 8; ++p) {
        const int src = 4 * p + sub;
        const int ip = myidxi[src];
        const int jp = myidxj[src];
        const float4* arow = reinterpret_cast<const float4*>(g_A + (size_t)ip * H1D);
        const float4* brow = reinterpret_cast<const float4*>(g_B + (size_t)jp * H1D);
        const float4 a0 = arow[2 * lc8], a1 = arow[2 * lc8 + 1];
        const float4 b0 = brow[2 * lc8], b1 = brow[2 * lc8 + 1];
        float s0 = a0.x + b0.x, s1 = a0.y + b0.y, s2 = a0.z + b0.z, s3 = a0.w + b0.w;
        float s4 = a1.x + b1.x, s5 = a1.y + b1.y, s6 = a1.z + b1.z, s7 = a1.w + b1.w;
        float sum = ((s0 + s1) + (s2 + s3)) + ((s4 + s5) + (s6 + s7));
        float sq  = fmaf(s0, s0, fmaf(s1, s1, fmaf(s2, s2, s3 * s3)))
                  + fmaf(s4, s4, fmaf(s5, s5, fmaf(s6, s6, s7 * s7)));
#pragma unroll
        for (int mk = 1; mk <= 4; mk <<= 1) {
            sum += __shfl_xor_sync(0xffffffffu, sum, mk);
            sq  += __shfl_xor_sync(0xffffffffu, sq,  mk);
        }
        const float mu  = sum * (1.f / H1D);
        const float inv = rsqrtf(sq * (1.f / H1D) - mu * mu + LN_EPS);
        const float4 ga = *reinterpret_cast<const float4*>(&g1s[8 * lc8]);
        const float4 gb = *reinterpret_cast<const float4*>(&g1s[8 * lc8 + 4]);
        const float4 ea = *reinterpret_cast<const float4*>(&be1s[8 * lc8]);
        const float4 eb = *reinterpret_cast<const float4*>(&be1s[8 * lc8 + 4]);
        const float t0 = fmaxf(fmaf((s0 - mu) * inv, ga.x, ea.x), 0.f);
        const float t1 = fmaxf(fmaf((s1 - mu) * inv, ga.y, ea.y), 0.f);
        const float t2 = fmaxf(fmaf((s2 - mu) * inv, ga.z, ea.z), 0.f);
        const float t3 = fmaxf(fmaf((s3 - mu) * inv, ga.w, ea.w), 0.f);
        const float t4 = fmaxf(fmaf((s4 - mu) * inv, gb.x, eb.x), 0.f);
        const float t5 = fmaxf(fmaf((s5 - mu) * inv, gb.y, eb.y), 0.f);
        const float t6 = fmaxf(fmaf((s6 - mu) * inv, gb.z, eb.z), 0.f);
        const float t7 = fmaxf(fmaf((s7 - mu) * inv, gb.w, eb.w), 0.f);
        uint4 pk;
        pk.x = packh2(t0, t1); pk.y = packh2(t2, t3);
        pk.z = packh2(t4, t5); pk.w = packh2(t6, t7);
        *reinterpret_cast<uint4*>(h1w + src * ROWP + 8 * lc8) = pk;
    }
    __syncwarp();

    // Layer 2 + epilogue per 16-pair M-tile. Diag staged in OWN h1 region.
    const int lrow  = (lane & 7) | (((lane >> 3) & 1) << 3);
    const int lcol8 = ((lane >> 4) & 1) * 8;
    const uint32_t h1base = smem_u32(h1w) + (uint32_t)(lrow * ROWP + lcol8) * 2u;
    float* diagw = reinterpret_cast<float*>(h1w);

#pragma unroll
    for (int m = 0; m < 2; ++m) {
        float acc[4][4];
#pragma unroll
        for (int t = 0; t < 4; ++t)
#pragma unroll
            for (int e = 0; e < 4; ++e) acc[t][e] = 0.f;
#pragma unroll
        for (int s = 0; s < 4; ++s) {
            uint32_t a0, a1, a2, a3;
            ldmatrix_x4(a0, a1, a2, a3,
                        h1base + (uint32_t)((16 * m * ROWP + 16 * s) * 2));
#pragma unroll
            for (int t = 0; t < 4; ++t) {
                const uint2 f = W2fr[(s * 4 + t) * 32 + lane];
                mma16816(acc[t], a0, a1, a2, a3, f.x, f.y);
            }
        }

        float v[4][4];
        float sum0 = 0.f, sq0 = 0.f, sum1 = 0.f, sq1 = 0.f;
#pragma unroll
        for (int t = 0; t < 4; ++t) {
            const int n0 = 8 * t + 2 * qr;
            const float bb0 = b2s[n0], bb1 = b2s[n0 + 1];
            v[t][0] = acc[t][0] + bb0;
            v[t][1] = acc[t][1] + bb1;
            v[t][2] = acc[t][2] + bb0;
            v[t][3] = acc[t][3] + bb1;
            sum0 += v[t][0] + v[t][1];
            sq0 = fmaf(v[t][0], v[t][0], fmaf(v[t][1], v[t][1], sq0));
            sum1 += v[t][2] + v[t][3];
            sq1 = fmaf(v[t][2], v[t][2], fmaf(v[t][3], v[t][3], sq1));
        }
#pragma unroll
        for (int mk = 1; mk <= 2; mk <<= 1) {
            sum0 += __shfl_xor_sync(0xffffffffu, sum0, mk);
            sq0  += __shfl_xor_sync(0xffffffffu, sq0,  mk);
            sum1 += __shfl_xor_sync(0xffffffffu, sum1, mk);
            sq1  += __shfl_xor_sync(0xffffffffu, sq1,  mk);
        }
        const float mu0  = sum0 * (1.f / H2D);
        const float inv0 = rsqrtf(sq0 * (1.f / H2D) - mu0 * mu0 + LN_EPS);
        const float mu1  = sum1 * (1.f / H2D);
        const float inv1 = rsqrtf(sq1 * (1.f / H2D) - mu1 * mu1 + LN_EPS);

        uint32_t a3f[4][2];
#pragma unroll
        for (int t = 0; t < 4; ++t) {
            const int n0 = 8 * t + 2 * qr;
            const float gg0 = g2s[n0], gg1 = g2s[n0 + 1];
            const float e0 = be2s[n0], e1 = be2s[n0 + 1];
            const float h0 = fmaxf(fmaf((v[t][0] - mu0) * inv0, gg0, e0), 0.f);
            const float h1v = fmaxf(fmaf((v[t][1] - mu0) * inv0, gg1, e1), 0.f);
            const float h2v = fmaxf(fmaf((v[t][2] - mu1) * inv1, gg0, e0), 0.f);
            const float h3v = fmaxf(fmaf((v[t][3] - mu1) * inv1, gg1, e1), 0.f);
            a3f[t][0] = packh2(h0, h1v);
            a3f[t][1] = packh2(h2v, h3v);
        }

        float d[2][4];
#pragma unroll
        for (int u = 0; u < 2; ++u) {
            const int n0 = 8 * u + 2 * qr;
            d[u][0] = b3s[n0]; d[u][1] = b3s[n0 + 1];
            d[u][2] = b3s[n0]; d[u][3] = b3s[n0 + 1];
        }
#pragma unroll
        for (int s = 0; s < 2; ++s) {
#pragma unroll
            for (int u = 0; u < 2; ++u) {
                const uint2 f = W3fr[(s * 2 + u) * 32 + lane];
                mma16816(d[u], a3f[2 * s][0], a3f[2 * s][1],
                         a3f[2 * s + 1][0], a3f[2 * s + 1][1], f.x, f.y);
            }
        }

        const int r0 = 16 * m + qc;
#pragma unroll
        for (int u = 0; u < 2; ++u) {
            const int n0 = 8 * u + 2 * qr;
            diagw[r0 * 17 + n0]           = d[u][0];
            diagw[r0 * 17 + n0 + 1]       = d[u][1];
            diagw[(r0 + 8) * 17 + n0]     = d[u][2];
            diagw[(r0 + 8) * 17 + n0 + 1] = d[u][3];
        }
    }
    __syncwarp();

    // Warp-autonomous store: this warp's 32 pairs = contiguous 2048 float4.
    const float* diagr = reinterpret_cast<const float*>(h1w);
    const int w4a = lane,       w4b = lane + 32;
    const int rowa = w4a >> 2,  rowb = w4b >> 2;
    const int dsela = rowa - (w4a & 3) * 4;
    const int dselb = rowb - (w4b & 3) * 4;
    const bool minea = (dsela >= 0) && (dsela < 4);
    const bool mineb = (dselb >= 0) && (dselb < 4);
    const float mxa = (dsela == 0) ? 1.f : 0.f, mya = (dsela == 1) ? 1.f : 0.f;
    const float mza = (dsela == 2) ? 1.f : 0.f, mwa = (dsela == 3) ? 1.f : 0.f;
    const float mxb = (dselb == 0) ? 1.f : 0.f, myb = (dselb == 1) ? 1.f : 0.f;
    const float mzb = (dselb == 2) ? 1.f : 0.f, mwb = (dselb == 3) ? 1.f : 0.f;
    const size_t warpBase4 = (size_t)blockIdx.x * (128 * 64) + (size_t)warp * (32 * 64);
    const size_t total4 = (size_t)P * 64;
    float4* o4p = reinterpret_cast<float4*>(out) + warpBase4;

    if (warpBase4 + 2048 <= total4) {
#pragma unroll 8
        for (int lp = 0; lp < 32; ++lp) {
            const size_t o = (size_t)lp * 64;
            float va = 0.f, vb = 0.f;
            if (minea) va = diagr[lp * 17 + rowa];
            if (mineb) vb = diagr[lp * 17 + rowb];
            float4 qa, qb;
            qa.x = va * mxa; qa.y = va * mya; qa.z = va * mza; qa.w = va * mwa;
            qb.x = vb * mxb; qb.y = vb * myb; qb.z = vb * mzb; qb.w = vb * mwb;
            __stcs(o4p + o + lane, qa);
            __stcs(o4p + o + 32 + lane, qb);
        }
    } else {
#pragma unroll 4
        for (int lp = 0; lp < 32; ++lp) {
            const size_t o = (size_t)lp * 64;
            float va = 0.f, vb = 0.f;
            if (minea) va = diagr[lp * 17 + rowa];
            if (mineb) vb = diagr[lp * 17 + rowb];
            if (warpBase4 + o + lane < total4) {
                float4 q;
                q.x = va * mxa; q.y = va * mya; q.z = va * mza; q.w = va * mwa;
                __stcs(o4p + o + lane, q);
            }
            if (warpBase4 + o + 32 + lane < total4) {
                float4 q;
                q.x = vb * mxb; q.y = vb * myb; q.z = vb * mzb; q.w = vb * mwb;
                __stcs(o4p + o + 32 + lane, q);
            }
        }
    }
}

extern "C" void kernel_launch(void* const* d_in, const int* in_sizes, int n_in,
                              void* d_out, int out_size) {
    const float* ef  = (const float*)d_in[0];
    const int*   pi  = (const int*)d_in[1];
    const int*   pj  = (const int*)d_in[2];
    const float* W1  = (const float*)d_in[3];
    const float* b1  = (const float*)d_in[4];
    const float* g1  = (const float*)d_in[5];
    const float* be1 = (const float*)d_in[6];
    const float* W2  = (const float*)d_in[7];
    const float* b2  = (const float*)d_in[8];
    const float* g2  = (const float*)d_in[9];
    const float* be2 = (const float*)d_in[10];
    const float* W3  = (const float*)d_in[11];
    const float* b3  = (const float*)d_in[12];
    float* out = (float*)d_out;

    const int E = in_sizes[0] / FD;
    const int P = in_sizes[1];

    precompute_kernel<<<(E + 127) / 128, 128>>>(ef, W1, b1, E);

    const int blocks = (P + 127) / 128;
    pairs_kernel<<<blocks, 128>>>(pi, pj, g1, be1, W2, b2, g2, be2, W3, b3, out, P);
}

// round 16
// speedup vs baseline: 1.0341x; 1.0341x over previous
#include <cuda_runtime.h>
#include <cuda_fp16.h>
#include <cstdint>

#define E_MAX 20000
#define FD 128
#define H1D 64
#define H2D 32
#define DD 16
#define LN_EPS 1e-5f
#define ROWP 72   // halves per h1 row (144 B): ldmatrix rows shift 4 banks/row

// Scratch: precomputed A = ef@W1[:128] + b1, B = ef@W1[128:]
__device__ float g_A[E_MAX * H1D];
__device__ float g_B[E_MAX * H1D];

// ---------------------------------------------------------------------------
// Helpers
// ---------------------------------------------------------------------------
__device__ __forceinline__ uint32_t smem_u32(const void* p) {
    return (uint32_t)__cvta_generic_to_shared(p);
}
__device__ __forceinline__ void ldmatrix_x4(uint32_t& a0, uint32_t& a1,
                                            uint32_t& a2, uint32_t& a3,
                                            uint32_t addr) {
    asm volatile("ldmatrix.sync.aligned.m8n8.x4.shared.b16 {%0,%1,%2,%3}, [%4];"
                 : "=r"(a0), "=r"(a1), "=r"(a2), "=r"(a3) : "r"(addr));
}
__device__ __forceinline__ void mma16816(float* c,
                                         uint32_t a0, uint32_t a1, uint32_t a2, uint32_t a3,
                                         uint32_t b0, uint32_t b1) {
    asm volatile("mma.sync.aligned.m16n8k16.row.col.f32.f16.f16.f32 "
                 "{%0,%1,%2,%3}, {%4,%5,%6,%7}, {%8,%9}, {%0,%1,%2,%3};"
                 : "+f"(c[0]), "+f"(c[1]), "+f"(c[2]), "+f"(c[3])
                 : "r"(a0), "r"(a1), "r"(a2), "r"(a3), "r"(b0), "r"(b1));
}
__device__ __forceinline__ uint32_t packh2(float lo, float hi) {
    __half2 h = __floats2half2_rn(lo, hi);
    return *reinterpret_cast<uint32_t*>(&h);
}

// ---------------------------------------------------------------------------
// Precompute via HMMA with ef hi/lo fp16 split — R13-exact config
// (32 edges/block, 625 blocks, direct-LDG fragment build), plus an early
// PDL trigger after this block's g_A/g_B stores.
// ---------------------------------------------------------------------------
__global__ void __launch_bounds__(128)
precompute_kernel(const float* __restrict__ ef,
                  const float* __restrict__ W1,
                  const float* __restrict__ b1,
                  int E) {
    __shared__ __half efhi[32 * FD];   // 8 KB, XOR-swizzled 16B chunks
    __shared__ __half eflo[32 * FD];   // 8 KB

    const int tid  = threadIdx.x;
    const int warp = tid >> 5;
    const int lane = tid & 31;
    const int qr   = lane & 3;
    const int qc   = lane >> 2;
    const int e0   = blockIdx.x * 32;

    // W' B-fragments in registers: wf[s][t] for kstep s, local ntile t.
    uint2 wf[8][4];
    float2 bias[4];
#pragma unroll
    for (int s = 0; s < 8; ++s)
#pragma unroll
        for (int t = 0; t < 4; ++t) {
            const int np = 8 * (4 * warp + t) + qc;
            const int k0 = 16 * s + 2 * qr;
            const int base = (np < H1D) ? 0 : FD;
            const int col  = (np < H1D) ? np : np - H1D;
            wf[s][t] = make_uint2(
                packh2(W1[(base + k0 + 0) * H1D + col], W1[(base + k0 + 1) * H1D + col]),
                packh2(W1[(base + k0 + 8) * H1D + col], W1[(base + k0 + 9) * H1D + col]));
        }
#pragma unroll
    for (int t = 0; t < 4; ++t) {
        if (warp < 2) {
            const int n0 = 8 * (4 * warp + t) + 2 * qr;
            bias[t] = make_float2(b1[n0], b1[n0 + 1]);
        } else {
            bias[t] = make_float2(0.f, 0.f);
        }
    }

    // Stage ef tile: 4 threads per edge row, hi/lo fp16 split, XOR swizzle.
    {
        const int r  = tid >> 2;
        const int kq = tid & 3;
        const int eg = e0 + r;
        const float4* src = reinterpret_cast<const float4*>(ef + (size_t)eg * FD);
#pragma unroll
        for (int q = 0; q < 4; ++q) {
            const int c = kq * 4 + q;
            float4 x0 = make_float4(0.f, 0.f, 0.f, 0.f), x1 = x0;
            if (eg < E) { x0 = src[c * 2]; x1 = src[c * 2 + 1]; }
            const float f[8] = {x0.x, x0.y, x0.z, x0.w, x1.x, x1.y, x1.z, x1.w};
            __half hh[8], hl[8];
#pragma unroll
            for (int i = 0; i < 8; ++i) {
                hh[i] = __float2half_rn(f[i]);
                hl[i] = __float2half_rn(f[i] - __half2float(hh[i]));
            }
            const int sc = c ^ (r & 7);
            *reinterpret_cast<uint4*>(&efhi[r * FD + sc * 8]) =
                *reinterpret_cast<const uint4*>(hh);
            *reinterpret_cast<uint4*>(&eflo[r * FD + sc * 8]) =
                *reinterpret_cast<const uint4*>(hl);
        }
    }
    __syncthreads();

    const int lrow = (lane & 7) | (((lane >> 3) & 1) << 3);
    const int cb   = (lane >> 4) & 1;
    const uint32_t hibase = smem_u32(efhi);
    const uint32_t lobase = smem_u32(eflo);

#pragma unroll
    for (int mt = 0; mt < 2; ++mt) {
        const int r2 = 16 * mt + lrow;
        const int rx = r2 & 7;
        float acc[4][4];
#pragma unroll
        for (int t = 0; t < 4; ++t)
#pragma unroll
            for (int e = 0; e < 4; ++e) acc[t][e] = 0.f;

#pragma unroll
        for (int s = 0; s < 8; ++s) {
            const uint32_t off =
                (uint32_t)(r2 * FD + ((2 * s + cb) ^ rx) * 8) * 2u;
            uint32_t h0, h1, h2, h3, l0, l1, l2, l3;
            ldmatrix_x4(h0, h1, h2, h3, hibase + off);
            ldmatrix_x4(l0, l1, l2, l3, lobase + off);
#pragma unroll
            for (int t = 0; t < 4; ++t) {
                mma16816(acc[t], h0, h1, h2, h3, wf[s][t].x, wf[s][t].y);
                mma16816(acc[t], l0, l1, l2, l3, wf[s][t].x, wf[s][t].y);
            }
        }

        const int rg0 = e0 + 16 * mt + qc;
        const int rg1 = rg0 + 8;
        float* const dst = (warp < 2) ? g_A : g_B;
#pragma unroll
        for (int t = 0; t < 4; ++t) {
            const int np  = 8 * (4 * warp + t) + 2 * qr;
            const int col = (warp < 2) ? np : np - H1D;
            if (rg0 < E) {
                *reinterpret_cast<float2*>(&dst[(size_t)rg0 * H1D + col]) =
                    make_float2(acc[t][0] + bias[t].x, acc[t][1] + bias[t].y);
            }
            if (rg1 < E) {
                *reinterpret_cast<float2*>(&dst[(size_t)rg1 * H1D + col]) =
                    make_float2(acc[t][2] + bias[t].x, acc[t][3] + bias[t].y);
            }
        }
    }

    // PDL: this block's output is written; allow the dependent grid to pass
    // its grid-dependency sync once every block has triggered.
    cudaTriggerProgrammaticLaunchCompletion();
}

// ---------------------------------------------------------------------------
// Main kernel: R14 pairs (best structure), launched with PDL. The preamble
// (weight fragments, LN params, pair indices) only touches kernel inputs,
// so it overlaps precompute; cudaGridDependencySynchronize() guards the
// first g_A/g_B read.
// ---------------------------------------------------------------------------
__global__ void __launch_bounds__(128, 8)
pairs_kernel(const int* __restrict__ pi, const int* __restrict__ pj,
             const float* __restrict__ g1, const float* __restrict__ be1,
             const float* __restrict__ W2, const float* __restrict__ b2,
             const float* __restrict__ g2, const float* __restrict__ be2,
             const float* __restrict__ W3, const float* __restrict__ b3,
             float* __restrict__ out, int P) {
    __shared__ __half h1[4][32 * ROWP];     // 18432 B (aliased diag after use)
    __shared__ uint2 W2fr[4 * 4 * 32];      // 4096 B: [s][t][lane]
    __shared__ uint2 W3fr[2 * 2 * 32];      // 1024 B: [s][u][lane]
    __shared__ float g1s[H1D], be1s[H1D], b2s[H2D], g2s[H2D], be2s[H2D], b3s[DD];
    __shared__ int sidxi[128], sidxj[128];

    const int tid  = threadIdx.x;
    const int warp = tid >> 5;
    const int lane = tid & 31;
    const int qr   = lane & 3;
    const int qc   = lane >> 2;

    for (int idx = tid; idx < 4 * 4 * 32; idx += 128) {
        const int ln = idx & 31, t = (idx >> 5) & 3, s = idx >> 7;
        const int k0 = 16 * s + 2 * (ln & 3);
        const int n  = 8 * t + (ln >> 2);
        W2fr[idx] = make_uint2(
            packh2(W2[(k0 + 0) * H2D + n], W2[(k0 + 1) * H2D + n]),
            packh2(W2[(k0 + 8) * H2D + n], W2[(k0 + 9) * H2D + n]));
    }
    if (tid < 2 * 2 * 32) {
        const int idx = tid;
        const int ln = idx & 31, u = (idx >> 5) & 1, s = idx >> 6;
        const int k0 = 16 * s + 2 * (ln & 3);
        const int n  = 8 * u + (ln >> 2);
        W3fr[idx] = make_uint2(
            packh2(W3[(k0 + 0) * DD + n], W3[(k0 + 1) * DD + n]),
            packh2(W3[(k0 + 8) * DD + n], W3[(k0 + 9) * DD + n]));
    }
    if (tid < H1D) { g1s[tid] = g1[tid]; be1s[tid] = be1[tid]; }
    if (tid < H2D) { b2s[tid] = b2[tid]; g2s[tid] = g2[tid]; be2s[tid] = be2[tid]; }
    if (tid < DD)  { b3s[tid] = b3[tid]; }
    {
        const int gp = blockIdx.x * 128 + tid;
        const int safe = (gp < P) ? gp : 0;
        sidxi[tid] = pi[safe];
        sidxj[tid] = pj[safe];
    }
    __syncthreads();

    // Wait for precompute's g_A/g_B before the gather.
    cudaGridDependencySynchronize();

    // Gather + fused LN1: 4 pairs/iter; 8 lanes per pair cover 8 channels.
    const int lc8 = lane & 7;
    const int sub = lane >> 3;
    __half* h1w = h1[warp];
    const int* myidxi = sidxi + warp * 32;
    const int* myidxj = sidxj + warp * 32;

#pragma unroll
    for (int p = 0; p < 8; ++p) {
        const int src = 4 * p + sub;
        const int ip = myidxi[src];
        const int jp = myidxj[src];
        const float4* arow = reinterpret_cast<const float4*>(g_A + (size_t)ip * H1D);
        const float4* brow = reinterpret_cast<const float4*>(g_B + (size_t)jp * H1D);
        const float4 a0 = arow[2 * lc8], a1 = arow[2 * lc8 + 1];
        const float4 b0 = brow[2 * lc8], b1 = brow[2 * lc8 + 1];
        float s0 = a0.x + b0.x, s1 = a0.y + b0.y, s2 = a0.z + b0.z, s3 = a0.w + b0.w;
        float s4 = a1.x + b1.x, s5 = a1.y + b1.y, s6 = a1.z + b1.z, s7 = a1.w + b1.w;
        float sum = ((s0 + s1) + (s2 + s3)) + ((s4 + s5) + (s6 + s7));
        float sq  = fmaf(s0, s0, fmaf(s1, s1, fmaf(s2, s2, s3 * s3)))
                  + fmaf(s4, s4, fmaf(s5, s5, fmaf(s6, s6, s7 * s7)));
#pragma unroll
        for (int mk = 1; mk <= 4; mk <<= 1) {
            sum += __shfl_xor_sync(0xffffffffu, sum, mk);
            sq  += __shfl_xor_sync(0xffffffffu, sq,  mk);
        }
        const float mu  = sum * (1.f / H1D);
        const float inv = rsqrtf(sq * (1.f / H1D) - mu * mu + LN_EPS);
        const float4 ga = *reinterpret_cast<const float4*>(&g1s[8 * lc8]);
        const float4 gb = *reinterpret_cast<const float4*>(&g1s[8 * lc8 + 4]);
        const float4 ea = *reinterpret_cast<const float4*>(&be1s[8 * lc8]);
        const float4 eb = *reinterpret_cast<const float4*>(&be1s[8 * lc8 + 4]);
        const float t0 = fmaxf(fmaf((s0 - mu) * inv, ga.x, ea.x), 0.f);
        const float t1 = fmaxf(fmaf((s1 - mu) * inv, ga.y, ea.y), 0.f);
        const float t2 = fmaxf(fmaf((s2 - mu) * inv, ga.z, ea.z), 0.f);
        const float t3 = fmaxf(fmaf((s3 - mu) * inv, ga.w, ea.w), 0.f);
        const float t4 = fmaxf(fmaf((s4 - mu) * inv, gb.x, eb.x), 0.f);
        const float t5 = fmaxf(fmaf((s5 - mu) * inv, gb.y, eb.y), 0.f);
        const float t6 = fmaxf(fmaf((s6 - mu) * inv, gb.z, eb.z), 0.f);
        const float t7 = fmaxf(fmaf((s7 - mu) * inv, gb.w, eb.w), 0.f);
        uint4 pk;
        pk.x = packh2(t0, t1); pk.y = packh2(t2, t3);
        pk.z = packh2(t4, t5); pk.w = packh2(t6, t7);
        *reinterpret_cast<uint4*>(h1w + src * ROWP + 8 * lc8) = pk;
    }
    __syncwarp();

    // Layer 2 + epilogue per 16-pair M-tile. Diag staged in OWN h1 region.
    const int lrow  = (lane & 7) | (((lane >> 3) & 1) << 3);
    const int lcol8 = ((lane >> 4) & 1) * 8;
    const uint32_t h1base = smem_u32(h1w) + (uint32_t)(lrow * ROWP + lcol8) * 2u;
    float* diagw = reinterpret_cast<float*>(h1w);

#pragma unroll
    for (int m = 0; m < 2; ++m) {
        float acc[4][4];
#pragma unroll
        for (int t = 0; t < 4; ++t)
#pragma unroll
            for (int e = 0; e < 4; ++e) acc[t][e] = 0.f;
#pragma unroll
        for (int s = 0; s < 4; ++s) {
            uint32_t a0, a1, a2, a3;
            ldmatrix_x4(a0, a1, a2, a3,
                        h1base + (uint32_t)((16 * m * ROWP + 16 * s) * 2));
#pragma unroll
            for (int t = 0; t < 4; ++t) {
                const uint2 f = W2fr[(s * 4 + t) * 32 + lane];
                mma16816(acc[t], a0, a1, a2, a3, f.x, f.y);
            }
        }

        float v[4][4];
        float sum0 = 0.f, sq0 = 0.f, sum1 = 0.f, sq1 = 0.f;
#pragma unroll
        for (int t = 0; t < 4; ++t) {
            const int n0 = 8 * t + 2 * qr;
            const float bb0 = b2s[n0], bb1 = b2s[n0 + 1];
            v[t][0] = acc[t][0] + bb0;
            v[t][1] = acc[t][1] + bb1;
            v[t][2] = acc[t][2] + bb0;
            v[t][3] = acc[t][3] + bb1;
            sum0 += v[t][0] + v[t][1];
            sq0 = fmaf(v[t][0], v[t][0], fmaf(v[t][1], v[t][1], sq0));
            sum1 += v[t][2] + v[t][3];
            sq1 = fmaf(v[t][2], v[t][2], fmaf(v[t][3], v[t][3], sq1));
        }
#pragma unroll
        for (int mk = 1; mk <= 2; mk <<= 1) {
            sum0 += __shfl_xor_sync(0xffffffffu, sum0, mk);
            sq0  += __shfl_xor_sync(0xffffffffu, sq0,  mk);
            sum1 += __shfl_xor_sync(0xffffffffu, sum1, mk);
            sq1  += __shfl_xor_sync(0xffffffffu, sq1,  mk);
        }
        const float mu0  = sum0 * (1.f / H2D);
        const float inv0 = rsqrtf(sq0 * (1.f / H2D) - mu0 * mu0 + LN_EPS);
        const float mu1  = sum1 * (1.f / H2D);
        const float inv1 = rsqrtf(sq1 * (1.f / H2D) - mu1 * mu1 + LN_EPS);

        uint32_t a3f[4][2];
#pragma unroll
        for (int t = 0; t < 4; ++t) {
            const int n0 = 8 * t + 2 * qr;
            const float gg0 = g2s[n0], gg1 = g2s[n0 + 1];
            const float e0 = be2s[n0], e1 = be2s[n0 + 1];
            const float h0 = fmaxf(fmaf((v[t][0] - mu0) * inv0, gg0, e0), 0.f);
            const float h1v = fmaxf(fmaf((v[t][1] - mu0) * inv0, gg1, e1), 0.f);
            const float h2v = fmaxf(fmaf((v[t][2] - mu1) * inv1, gg0, e0), 0.f);
            const float h3v = fmaxf(fmaf((v[t][3] - mu1) * inv1, gg1, e1), 0.f);
            a3f[t][0] = packh2(h0, h1v);
            a3f[t][1] = packh2(h2v, h3v);
        }

        float d[2][4];
#pragma unroll
        for (int u = 0; u < 2; ++u) {
            const int n0 = 8 * u + 2 * qr;
            d[u][0] = b3s[n0]; d[u][1] = b3s[n0 + 1];
            d[u][2] = b3s[n0]; d[u][3] = b3s[n0 + 1];
        }
#pragma unroll
        for (int s = 0; s < 2; ++s) {
#pragma unroll
            for (int u = 0; u < 2; ++u) {
                const uint2 f = W3fr[(s * 2 + u) * 32 + lane];
                mma16816(d[u], a3f[2 * s][0], a3f[2 * s][1],
                         a3f[2 * s + 1][0], a3f[2 * s + 1][1], f.x, f.y);
            }
        }

        const int r0 = 16 * m + qc;
#pragma unroll
        for (int u = 0; u < 2; ++u) {
            const int n0 = 8 * u + 2 * qr;
            diagw[r0 * 17 + n0]           = d[u][0];
            diagw[r0 * 17 + n0 + 1]       = d[u][1];
            diagw[(r0 + 8) * 17 + n0]     = d[u][2];
            diagw[(r0 + 8) * 17 + n0 + 1] = d[u][3];
        }
    }
    __syncwarp();

    // Warp-autonomous store: this warp's 32 pairs = contiguous 2048 float4.
    const float* diagr = reinterpret_cast<const float*>(h1w);
    const int w4a = lane,       w4b = lane + 32;
    const int rowa = w4a >> 2,  rowb = w4b >> 2;
    const int dsela = rowa - (w4a & 3) * 4;
    const int dselb = rowb - (w4b & 3) * 4;
    const bool minea = (dsela >= 0) && (dsela < 4);
    const bool mineb = (dselb >= 0) && (dselb < 4);
    const float mxa = (dsela == 0) ? 1.f : 0.f, mya = (dsela == 1) ? 1.f : 0.f;
    const float mza = (dsela == 2) ? 1.f : 0.f, mwa = (dsela == 3) ? 1.f : 0.f;
    const float mxb = (dselb == 0) ? 1.f : 0.f, myb = (dselb == 1) ? 1.f : 0.f;
    const float mzb = (dselb == 2) ? 1.f : 0.f, mwb = (dselb == 3) ? 1.f : 0.f;
    const size_t warpBase4 = (size_t)blockIdx.x * (128 * 64) + (size_t)warp * (32 * 64);
    const size_t total4 = (size_t)P * 64;
    float4* o4p = reinterpret_cast<float4*>(out) + warpBase4;

    if (warpBase4 + 2048 <= total4) {
#pragma unroll 8
        for (int lp = 0; lp < 32; ++lp) {
            const size_t o = (size_t)lp * 64;
            float va = 0.f, vb = 0.f;
            if (minea) va = diagr[lp * 17 + rowa];
            if (mineb) vb = diagr[lp * 17 + rowb];
            float4 qa, qb;
            qa.x = va * mxa; qa.y = va * mya; qa.z = va * mza; qa.w = va * mwa;
            qb.x = vb * mxb; qb.y = vb * myb; qb.z = vb * mzb; qb.w = vb * mwb;
            __stcs(o4p + o + lane, qa);
            __stcs(o4p + o + 32 + lane, qb);
        }
    } else {
#pragma unroll 4
        for (int lp = 0; lp < 32; ++lp) {
            const size_t o = (size_t)lp * 64;
            float va = 0.f, vb = 0.f;
            if (minea) va = diagr[lp * 17 + rowa];
            if (mineb) vb = diagr[lp * 17 + rowb];
            if (warpBase4 + o + lane < total4) {
                float4 q;
                q.x = va * mxa; q.y = va * mya; q.z = va * mza; q.w = va * mwa;
                __stcs(o4p + o + lane, q);
            }
            if (warpBase4 + o + 32 + lane < total4) {
                float4 q;
                q.x = vb * mxb; q.y = vb * myb; q.z = vb * mzb; q.w = vb * mwb;
                __stcs(o4p + o + 32 + lane, q);
            }
        }
    }
}

extern "C" void kernel_launch(void* const* d_in, const int* in_sizes, int n_in,
                              void* d_out, int out_size) {
    const float* ef  = (const float*)d_in[0];
    const int*   pi  = (const int*)d_in[1];
    const int*   pj  = (const int*)d_in[2];
    const float* W1  = (const float*)d_in[3];
    const float* b1  = (const float*)d_in[4];
    const float* g1  = (const float*)d_in[5];
    const float* be1 = (const float*)d_in[6];
    const float* W2  = (const float*)d_in[7];
    const float* b2  = (const float*)d_in[8];
    const float* g2  = (const float*)d_in[9];
    const float* be2 = (const float*)d_in[10];
    const float* W3  = (const float*)d_in[11];
    const float* b3  = (const float*)d_in[12];
    float* out = (float*)d_out;

    const int E = in_sizes[0] / FD;
    const int P = in_sizes[1];

    precompute_kernel<<<(E + 31) / 32, 128>>>(ef, W1, b1, E);

    // PDL launch: pairs_kernel may start while precompute runs; its
    // grid-dependency sync gates the g_A/g_B reads.
    cudaLaunchConfig_t cfg = {};
    cfg.gridDim  = dim3((P + 127) / 128, 1, 1);
    cfg.blockDim = dim3(128, 1, 1);
    cfg.dynamicSmemBytes = 0;
    cudaLaunchAttribute attrs[1];
    attrs[0].id = cudaLaunchAttributeProgrammaticStreamSerialization;
    attrs[0].val.programmaticStreamSerializationAllowed = 1;
    cfg.attrs = attrs;
    cfg.numAttrs = 1;
    cudaLaunchKernelEx(&cfg, pairs_kernel,
                       pi, pj, g1, be1, W2, b2, g2, be2, W3, b3, out, P);
}